// round 12
// baseline (speedup 1.0000x reference)
#include <cuda_runtime.h>
#include <cuda_fp16.h>

#define BB 4
#define AA 512
#define DD 729
#define HH 512
#define WW 512

// Batch-AoS fp16 buffer: for each (angle a, det index i), 16 bytes =
// 4 batches x (v[i], v[i+1]-v[i]) as half2. One LDG.128 fetches all 4
// batches; interp = v0 + delta*f via one HFMA2 with weight (1, f).
// Padded by one angle-row so the pipeline's final prefetch (a+1 == AA)
// stays in-bounds (the prefetched value is never consumed).
__device__ __align__(16) __half2 g_pairs[(AA + 1) * DD * BB];
// Per-angle (cos/dsp, sin/dsp).
__device__ __align__(16) float2 g_trig[AA];

// One thread per (a, i). First 512 threads also build the trig table.
__global__ void build_pairs_kernel(const float* __restrict__ sino,
                                   const float* __restrict__ traj,
                                   const float* __restrict__ det_sp) {
    int idx = blockIdx.x * blockDim.x + threadIdx.x;  // idx = a*DD + i
    if (idx < AA) {
        float inv = 1.0f / det_sp[0];
        float th = traj[idx];
        g_trig[idx] = make_float2(cosf(th) * inv, sinf(th) * inv);
    }
    const int total = AA * DD;
    if (idx >= total) return;
    int i = idx % DD;
    bool has_next = (i < DD - 1);

    uint4 out;
    unsigned* po = (unsigned*)&out;
#pragma unroll
    for (int b = 0; b < BB; ++b) {
        const float* p = sino + (size_t)b * (AA * DD) + idx;
        float v0 = p[0];
        float v1 = has_next ? p[1] : 0.0f;
        __half2 h = __floats2half2_rn(v0, v1 - v0);  // (v0, delta)
        po[b] = *(unsigned*)&h;
    }
    ((uint4*)g_pairs)[idx] = out;
}

// 256 threads/block over a 16x16 pixel tile; each WARP covers 8(x) x 4(y)
// pixels. Grid (32,32)=1024 blocks. Software-pipelined gather: the LDG for
// angle a+1 is issued BEFORE angle a's value is consumed, putting a full
// angle-body of issue distance between each load and its use. Packed fp16
// interp (HFMA2), flushed to fp32 every 4 angles (HADD + cvt).
// launch_bounds(256,8) pins regs at 32 (occupancy invariant).
__global__ __launch_bounds__(256, 8)
void backproject_kernel(const float* __restrict__ vol_origin,
                        const float* __restrict__ det_origin,
                        const float* __restrict__ vol_sp,
                        const float* __restrict__ det_sp,
                        float* __restrict__ out) {
    __shared__ __align__(16) float2 s_trig[AA + 8];  // padded for prefetch

    const int tid = threadIdx.x;
    {
        const float4* gt = (const float4*)g_trig;
        float4* st = (float4*)s_trig;
        for (int a = tid; a < AA / 2; a += 256) st[a] = gt[a];
        if (tid < 8) s_trig[AA + tid] = make_float2(0.f, 0.f);  // pad: u=K
    }
    __syncthreads();

    const int w    = tid >> 5;
    const int lane = tid & 31;
    const int lx   = lane & 7;
    const int ly   = lane >> 3;
    const int wx   = w & 1;
    const int wy   = w >> 1;

    const int x = blockIdx.x * 16 + wx * 8 + lx;
    const int y = blockIdx.y * 16 + wy * 4 + ly;

    const float xs = vol_origin[1] + (float)x * vol_sp[1];
    const float ys = vol_origin[0] + (float)y * vol_sp[0];
    const float K  = -det_origin[0] / det_sp[0];

    float acc0 = 0.f, acc1 = 0.f, acc2 = 0.f, acc3 = 0.f;
    __half2 h0 = __float2half2_rn(0.f);
    __half2 h1 = h0, h2 = h0, h3 = h0;

    const uint4* __restrict__ base = (const uint4*)g_pairs;

    // Pipeline prologue: load angle 0.
    uint4 pc;
    float fc;
    {
        const float2 t = s_trig[0];
        const float u  = fmaf(xs, t.x, fmaf(ys, t.y, K));
        const int   i0 = (int)u;            // u in [2.7,725.3]: trunc==floor
        fc = u - truncf(u);
        pc = __ldg(base + i0);
    }

#pragma unroll 8
    for (int a = 0; a < AA; ++a) {
        // ---- prefetch angle a+1 (final iteration reads padded region,
        //      value never consumed) ----
        const float2 t = s_trig[a + 1];
        const float un = fmaf(xs, t.x, fmaf(ys, t.y, K));
        const int  i0n = (int)un;
        const float fn = un - truncf(un);
        const uint4 pn = __ldg(base + (a + 1) * DD + i0n);

        // ---- consume angle a ----
        const __half2 wgt = __floats2half2_rn(1.0f, fc);
        h0 = __hfma2(*(const __half2*)&pc.x, wgt, h0);
        h1 = __hfma2(*(const __half2*)&pc.y, wgt, h1);
        h2 = __hfma2(*(const __half2*)&pc.z, wgt, h2);
        h3 = __hfma2(*(const __half2*)&pc.w, wgt, h3);

        if ((a & 3) == 3) {  // compile-time under unroll 8
            acc0 += __half2float(__hadd(__low2half(h0), __high2half(h0)));
            acc1 += __half2float(__hadd(__low2half(h1), __high2half(h1)));
            acc2 += __half2float(__hadd(__low2half(h2), __high2half(h2)));
            acc3 += __half2float(__hadd(__low2half(h3), __high2half(h3)));
            h0 = __float2half2_rn(0.f);
            h1 = h0; h2 = h0; h3 = h0;
        }

        pc = pn;
        fc = fn;
    }

    const size_t px = (size_t)y * WW + x;
    out[px]                       = acc0;
    out[px + (size_t)HH * WW]     = acc1;
    out[px + (size_t)2 * HH * WW] = acc2;
    out[px + (size_t)3 * HH * WW] = acc3;
}

extern "C" void kernel_launch(void* const* d_in, const int* in_sizes, int n_in,
                              void* d_out, int out_size) {
    const float* sino       = (const float*)d_in[0];
    const float* vol_origin = (const float*)d_in[2];
    const float* det_origin = (const float*)d_in[3];
    const float* vol_sp     = (const float*)d_in[4];
    const float* det_sp     = (const float*)d_in[5];
    const float* traj       = (const float*)d_in[6];
    float* out = (float*)d_out;

    const int total = AA * DD;
    build_pairs_kernel<<<(total + 255) / 256, 256>>>(sino, traj, det_sp);

    dim3 blk(256);
    dim3 grd(WW / 16, HH / 16);
    backproject_kernel<<<grd, blk>>>(vol_origin, det_origin, vol_sp, det_sp, out);
}

// round 13
// speedup vs baseline: 1.0412x; 1.0412x over previous
#include <cuda_runtime.h>
#include <cuda_fp16.h>

#define BB 4
#define AA 512
#define DD 729
#define HH 512
#define WW 512

// Batch-AoS fp16 buffer: for each (angle a, det index i), 16 bytes =
// 4 batches x (v[i], v[i+1]-v[i]) as half2. One LDG.128 fetches all 4
// batches; interp = v0 + delta*f via one HFMA2 with weight (1, f).
// Padded by TWO angle-rows so the double-buffered pipeline's deepest
// prefetch (a+2 == AA+1) stays in-bounds (values never consumed).
__device__ __align__(16) __half2 g_pairs[(AA + 2) * DD * BB];
// Per-angle (cos/dsp, sin/dsp).
__device__ __align__(16) float2 g_trig[AA];

// One thread per (a, i). First 512 threads also build the trig table.
__global__ void build_pairs_kernel(const float* __restrict__ sino,
                                   const float* __restrict__ traj,
                                   const float* __restrict__ det_sp) {
    int idx = blockIdx.x * blockDim.x + threadIdx.x;  // idx = a*DD + i
    if (idx < AA) {
        float inv = 1.0f / det_sp[0];
        float th = traj[idx];
        g_trig[idx] = make_float2(cosf(th) * inv, sinf(th) * inv);
    }
    const int total = AA * DD;
    if (idx >= total) return;
    int i = idx % DD;
    bool has_next = (i < DD - 1);

    uint4 out;
    unsigned* po = (unsigned*)&out;
#pragma unroll
    for (int b = 0; b < BB; ++b) {
        const float* p = sino + (size_t)b * (AA * DD) + idx;
        float v0 = p[0];
        float v1 = has_next ? p[1] : 0.0f;
        __half2 h = __floats2half2_rn(v0, v1 - v0);  // (v0, delta)
        po[b] = *(unsigned*)&h;
    }
    ((uint4*)g_pairs)[idx] = out;
}

// 256 threads/block over a 16x16 pixel tile; each WARP covers 8(x) x 4(y)
// pixels. Grid (32,32)=1024 blocks. Structurally double-buffered gather
// pipeline: buffers A/B alternate roles each half-iteration, so prefetch
// distance is a full consume-block with ZERO register copies (R11 lesson).
// Packed fp16 interp (HFMA2), flushed to fp32 every 4 angles (HADD + cvt).
// launch_bounds(256,7): 36-reg ceiling buys rename headroom; 1024 blocks /
// 148 SMs = 6.9 < 7 resident, so occupancy is unchanged vs the 8-block cap.
__global__ __launch_bounds__(256, 7)
void backproject_kernel(const float* __restrict__ vol_origin,
                        const float* __restrict__ det_origin,
                        const float* __restrict__ vol_sp,
                        const float* __restrict__ det_sp,
                        float* __restrict__ out) {
    __shared__ __align__(16) float2 s_trig[AA + 8];  // padded for prefetch

    const int tid = threadIdx.x;
    {
        const float4* gt = (const float4*)g_trig;
        float4* st = (float4*)s_trig;
        for (int a = tid; a < AA / 2; a += 256) st[a] = gt[a];
        if (tid < 8) s_trig[AA + tid] = make_float2(0.f, 0.f);  // pad: u=K
    }
    __syncthreads();

    const int w    = tid >> 5;
    const int lane = tid & 31;
    const int lx   = lane & 7;
    const int ly   = lane >> 3;
    const int wx   = w & 1;
    const int wy   = w >> 1;

    const int x = blockIdx.x * 16 + wx * 8 + lx;
    const int y = blockIdx.y * 16 + wy * 4 + ly;

    const float xs = vol_origin[1] + (float)x * vol_sp[1];
    const float ys = vol_origin[0] + (float)y * vol_sp[0];
    const float K  = -det_origin[0] / det_sp[0];

    float acc0 = 0.f, acc1 = 0.f, acc2 = 0.f, acc3 = 0.f;
    __half2 h0 = __float2half2_rn(0.f);
    __half2 h1 = h0, h2 = h0, h3 = h0;

    const uint4* __restrict__ base = (const uint4*)g_pairs;

    uint4 pA, pB;
    float fA, fB;

    // Pipeline prologue: load angle 0 into buffer A.
    {
        const float2 t = s_trig[0];
        const float u  = fmaf(xs, t.x, fmaf(ys, t.y, K));
        const int   i0 = (int)u;            // u in [2.7,725.3]: trunc==floor
        fA = u - (float)i0;
        pA = __ldg(base + i0);
    }

#pragma unroll 4
    for (int a = 0; a < AA; a += 2) {
        // ---- prefetch angle a+1 into B ----
        {
            const float2 t = s_trig[a + 1];
            const float u  = fmaf(xs, t.x, fmaf(ys, t.y, K));
            const int   i0 = (int)u;
            fB = u - (float)i0;
            pB = __ldg(base + (a + 1) * DD + i0);
        }
        // ---- consume angle a (buffer A) ----
        {
            const __half2 wgt = __floats2half2_rn(1.0f, fA);
            h0 = __hfma2(*(const __half2*)&pA.x, wgt, h0);
            h1 = __hfma2(*(const __half2*)&pA.y, wgt, h1);
            h2 = __hfma2(*(const __half2*)&pA.z, wgt, h2);
            h3 = __hfma2(*(const __half2*)&pA.w, wgt, h3);
        }
        // ---- prefetch angle a+2 into A (last iter hits padded rows) ----
        {
            const float2 t = s_trig[a + 2];
            const float u  = fmaf(xs, t.x, fmaf(ys, t.y, K));
            const int   i0 = (int)u;
            fA = u - (float)i0;
            pA = __ldg(base + (a + 2) * DD + i0);
        }
        // ---- consume angle a+1 (buffer B) ----
        {
            const __half2 wgt = __floats2half2_rn(1.0f, fB);
            h0 = __hfma2(*(const __half2*)&pB.x, wgt, h0);
            h1 = __hfma2(*(const __half2*)&pB.y, wgt, h1);
            h2 = __hfma2(*(const __half2*)&pB.z, wgt, h2);
            h3 = __hfma2(*(const __half2*)&pB.w, wgt, h3);
        }

        if (((a + 1) & 3) == 3) {  // static under unroll 4
            acc0 += __half2float(__hadd(__low2half(h0), __high2half(h0)));
            acc1 += __half2float(__hadd(__low2half(h1), __high2half(h1)));
            acc2 += __half2float(__hadd(__low2half(h2), __high2half(h2)));
            acc3 += __half2float(__hadd(__low2half(h3), __high2half(h3)));
            h0 = __float2half2_rn(0.f);
            h1 = h0; h2 = h0; h3 = h0;
        }
    }

    const size_t px = (size_t)y * WW + x;
    out[px]                       = acc0;
    out[px + (size_t)HH * WW]     = acc1;
    out[px + (size_t)2 * HH * WW] = acc2;
    out[px + (size_t)3 * HH * WW] = acc3;
}

extern "C" void kernel_launch(void* const* d_in, const int* in_sizes, int n_in,
                              void* d_out, int out_size) {
    const float* sino       = (const float*)d_in[0];
    const float* vol_origin = (const float*)d_in[2];
    const float* det_origin = (const float*)d_in[3];
    const float* vol_sp     = (const float*)d_in[4];
    const float* det_sp     = (const float*)d_in[5];
    const float* traj       = (const float*)d_in[6];
    float* out = (float*)d_out;

    const int total = AA * DD;
    build_pairs_kernel<<<(total + 255) / 256, 256>>>(sino, traj, det_sp);

    dim3 blk(256);
    dim3 grd(WW / 16, HH / 16);
    backproject_kernel<<<grd, blk>>>(vol_origin, det_origin, vol_sp, det_sp, out);
}